// round 12
// baseline (speedup 1.0000x reference)
#include <cuda_runtime.h>
#include <cstdint>

#define NGROUPS 512   // B*S/16
#define NSLOTS  64    // E*Sets
#define DDIM    512
#define TTOK    16
#define FDIM    32

typedef unsigned long long ull;
union U2 { ull u; float2 f; };

// packed fp32x2 FMA (route kernel)
__device__ __forceinline__ void ffma2(ull& d, ull a, ull b) {
    asm("fma.rn.f32x2 %0, %1, %2, %0;" : "+l"(d) : "l"(a), "l"(b));
}
__device__ __forceinline__ ull bcast2(float x) {
    ull r; asm("mov.b64 %0, {%1, %1};" : "=l"(r) : "f"(x)); return r;
}

__device__ int g_winners[NGROUPS * NSLOTS];
// pre-split operands: each ull = {bf16x2 hi-pair (low32) | bf16x2 residual (high32)}
__device__ ull g_xsplit[NGROUPS * TTOK * (DDIM / 2)];        // [8192 rows][256 kp]
__device__ ull g_f1split[(DDIM / 2) * 2048];                 // [256 kp][slot*32+f]
__device__ ull g_f2split[NSLOTS * (FDIM / 2) * DDIM];        // [slot][16 fp][512 d]

// ---------------------------------------------------------------------------
// bf16 split helpers
// ---------------------------------------------------------------------------
__device__ __forceinline__ uint32_t bf2_of(float v0, float v1) {
    uint32_t r;
    asm("cvt.rn.bf16x2.f32 %0, %1, %2;" : "=r"(r) : "f"(v1), "f"(v0));
    return r;
}
__device__ __forceinline__ ull splitpack(float v0, float v1) {
    const uint32_t h = bf2_of(v0, v1);
    const float r0 = v0 - __uint_as_float(h << 16);
    const float r1 = v1 - __uint_as_float(h & 0xffff0000u);
    const uint32_t l = bf2_of(r0, r1);
    return (ull)h | ((ull)l << 32);
}
__device__ __forceinline__ void mma16(float* c, uint32_t a0, uint32_t a1,
                                      uint32_t a2, uint32_t a3,
                                      uint32_t b0, uint32_t b1) {
    asm volatile("mma.sync.aligned.m16n8k16.row.col.f32.bf16.bf16.f32 "
                 "{%0,%1,%2,%3}, {%4,%5,%6,%7}, {%8,%9}, {%0,%1,%2,%3};"
                 : "+f"(c[0]), "+f"(c[1]), "+f"(c[2]), "+f"(c[3])
                 : "r"(a0), "r"(a1), "r"(a2), "r"(a3), "r"(b0), "r"(b1));
}
__device__ __forceinline__ uint32_t ulo(ull v) { return (uint32_t)v; }
__device__ __forceinline__ uint32_t uhi(ull v) { return (uint32_t)(v >> 32); }

// ---------------------------------------------------------------------------
// Kernel 0: pre-split f1 and f2 (runs once per launch; ~2us)
// ---------------------------------------------------------------------------
__global__ __launch_bounds__(256) void k_prep(const float* __restrict__ f1,
                                              const float* __restrict__ f2)
{
    const int i = blockIdx.x * 256 + threadIdx.x;
    if (i < 524288) {
        const int kp = i >> 11, sf = i & 2047;
        g_f1split[i] = splitpack(__ldg(f1 + (size_t)(2 * kp) * 2048 + sf),
                                 __ldg(f1 + (size_t)(2 * kp + 1) * 2048 + sf));
    } else {
        const int j = i - 524288;
        const int slot = j >> 13, fp = (j >> 9) & 15, d = j & 511;
        const float* base = f2 + (size_t)slot * 16384 + (size_t)(2 * fp) * 512 + d;
        g_f2split[j] = splitpack(__ldg(base), __ldg(base + 512));
    }
}

// ---------------------------------------------------------------------------
// Kernel 1: routing (proven exact) + writes g_xsplit from its smem tile.
// Zero-inits out.
// ---------------------------------------------------------------------------
__global__ __launch_bounds__(256) void k_route(const float* __restrict__ x,
                                               const float* __restrict__ ctrl,
                                               float* __restrict__ out)
{
    extern __shared__ float sm[];
    float* xs   = sm;
    float* part = sm + 8192;
    float* ls   = sm + 12288;
    double* dred = (double*)(sm + 13312);
    __shared__ int sflags[64];
    __shared__ int swin[64];
    __shared__ int snf;
    __shared__ double dlog[16];

    const int G   = blockIdx.x;
    const int tid = threadIdx.x;
    if (tid == 0) snf = 0;

    const float4* src = (const float4*)(x + (size_t)G * 8192);
    float4* dst = (float4*)(out + (size_t)G * 8192);
    float4* xs4 = (float4*)xs;
    const float4 z4 = make_float4(0.f, 0.f, 0.f, 0.f);
    for (int i = tid; i < 2048; i += 256) { xs4[i] = src[i]; dst[i] = z4; }
    __syncthreads();

    // write pre-split X rows (16 rows x 256 kp)
    for (int i = tid; i < 4096; i += 256) {
        const int r = i >> 8, kp = i & 255;
        g_xsplit[((size_t)G * 16 + r) * 256 + kp] =
            splitpack(xs[r * DDIM + 2 * kp], xs[r * DDIM + 2 * kp + 1]);
    }

    {
        const int sq = tid & 15;
        const int tq = (tid >> 4) & 3;
        const int ks = tid >> 6;
        const int kbase = ks * 128;
        U2 acc[4][2];
        #pragma unroll
        for (int t = 0; t < 4; ++t) { acc[t][0].u = 0ull; acc[t][1].u = 0ull; }
        const float* cbase = ctrl + sq * 4;
        const float* x0 = xs + tq * 4 * DDIM;
        for (int kk = 0; kk < 128; kk += 4) {
            const int k = kbase + kk;
            ulonglong2 w[4];
            #pragma unroll
            for (int j = 0; j < 4; ++j)
                w[j] = __ldg((const ulonglong2*)(cbase + (size_t)(k + j) * 64));
            float xv[4][4];
            #pragma unroll
            for (int t = 0; t < 4; ++t)
                *(float4*)&xv[t][0] = *(const float4*)(x0 + t * DDIM + k);
            #pragma unroll
            for (int j = 0; j < 4; ++j) {
                #pragma unroll
                for (int t = 0; t < 4; ++t) {
                    ull xb = bcast2(xv[t][j]);
                    ffma2(acc[t][0].u, xb, w[j].x);
                    ffma2(acc[t][1].u, xb, w[j].y);
                }
            }
        }
        #pragma unroll
        for (int t = 0; t < 4; ++t) {
            part[tid * 16 + t * 4 + 0] = acc[t][0].f.x;
            part[tid * 16 + t * 4 + 1] = acc[t][0].f.y;
            part[tid * 16 + t * 4 + 2] = acc[t][1].f.x;
            part[tid * 16 + t * 4 + 3] = acc[t][1].f.y;
        }
    }
    __syncthreads();

    {
        const int s   = tid & 63;
        const int tq2 = tid >> 6;
        const int sq2 = s >> 2, sl = s & 3;
        const float step = 1e-6f / 15.f;
        #pragma unroll
        for (int tl = 0; tl < 4; ++tl) {
            float v = 0.f;
            #pragma unroll
            for (int c = 0; c < 4; ++c)
                v += part[(c * 64 + tq2 * 16 + sq2) * 16 + tl * 4 + sl];
            const int t = tq2 * 4 + tl;
            ls[s * 16 + t] = v + step * (float)t;
        }
    }
    __syncthreads();

    if (tid < 64) {
        const int s = tid;
        float best = -3.4e38f, second = -3.4e38f;
        int bi = 0;
        #pragma unroll
        for (int t = 0; t < TTOK; ++t) {
            float v = ls[s * 16 + t];
            if (v >= best) { second = best; best = v; bi = t; }
            else if (v > second) { second = v; }
        }
        swin[s] = bi;
        if (best - second < 2e-5f) { int p = atomicAdd(&snf, 1); sflags[p] = s; }
    }
    __syncthreads();

    const int nf = snf;
    for (int i = 0; i < nf; ++i) {
        const int s = sflags[i];
        const int t = tid >> 4, j = tid & 15;
        double a = 0.0;
        const float* xr = xs + t * DDIM + j * 32;
        const float* cp = ctrl + (size_t)(j * 32) * 64 + s;
        #pragma unroll 8
        for (int k = 0; k < 32; ++k)
            a += (double)xr[k] * (double)__ldg(cp + (size_t)k * 64);
        dred[t * 16 + j] = a;
        __syncthreads();
        if (tid < 16) {
            double tot = 0.0;
            #pragma unroll
            for (int j2 = 0; j2 < 16; ++j2) tot += dred[tid * 16 + j2];
            dlog[tid] = tot + (double)tid * (1e-6 / 15.0);
        }
        __syncthreads();
        if (tid == 0) {
            double best = -1e300; int bi = 0;
            #pragma unroll
            for (int t2 = 0; t2 < TTOK; ++t2)
                if (dlog[t2] >= best) { best = dlog[t2]; bi = t2; }
            swin[s] = bi;
        }
        __syncthreads();
    }
    if (tid < 64) g_winners[G * 64 + tid] = swin[tid];
}

// ---------------------------------------------------------------------------
// Kernel 2: split-bf16 mma.sync expert, 128 thr / 4 warps, 64 rows/CTA.
// All operands PRE-SPLIT in global; staging is a pure LDG.128->ST.128 copy.
// Warp = one 16-row m-tile; GEMM1 C-fragments reused in regs as GEMM2 A.
// Smem layouts identical to R11 (conflict-free, stride 36/132 ull).
// ---------------------------------------------------------------------------
#define OFF_ROWB 0
#define OFF_B1   256
#define OFF_X    18688
#define SMEM2    55552

__global__ __launch_bounds__(128, 4) void k_expert(float* __restrict__ out)
{
    extern __shared__ __align__(16) char smraw[];
    int* rowb = (int*)(smraw + OFF_ROWB);      // in ull-word units (row*256)
    ull* B1b  = (ull*)(smraw + OFF_B1);        // [2][32*36]
    ull* Xb   = (ull*)(smraw + OFF_X);         // [2][64*36]
    ull* B2b  = (ull*)(smraw + OFF_X);         // [2][16*132] alias

    const int slot = blockIdx.y;
    const int g0   = blockIdx.x * 64;
    const int tid  = threadIdx.x;
    const int wid  = tid >> 5;
    const int lane = tid & 31;
    const int gq   = lane >> 2;
    const int c4   = lane & 3;

    if (tid < 64) {
        const int gg = g0 + tid;
        rowb[tid] = (gg * TTOK + g_winners[gg * 64 + slot]) * (DDIM / 2);
    }
    __syncthreads();

    const int m0 = wid * 16;

    // staging maps
    const int xr0 = tid >> 4;            // X base row (rows xr0+8p)
    const int xw  = (tid & 15) * 2;      // X word offset (2 words = 1 LDG.128)
    const int bkp = tid >> 2;            // B1 k-pair 0..31
    const int bf0 = (tid & 3) * 8;       // B1 f word base (8 words)
    const ull* f1s = g_f1split + slot * 32;
    const int b2kp = tid >> 3;           // B2 f-pair 0..15
    const int b2n  = (tid & 7) * 16;     // B2 n word base (16 words)
    const ull* f2s = g_f2split + (size_t)slot * 8192 + (size_t)b2kp * 512 + b2n;

    // ---- prefetch chunk 0
    ulonglong2 xv[8];
    ulonglong2 wv[4];
    #pragma unroll
    for (int p = 0; p < 8; ++p)
        xv[p] = __ldg((const ulonglong2*)&g_xsplit[rowb[xr0 + 8 * p] + xw]);
    #pragma unroll
    for (int e = 0; e < 4; ++e)
        wv[e] = __ldg((const ulonglong2*)&f1s[(size_t)bkp * 2048 + bf0 + 2 * e]);

    // stage chunk 0 into buf 0
    #pragma unroll
    for (int p = 0; p < 8; ++p)
        *(ulonglong2*)&Xb[(xr0 + 8 * p) * 36 + xw] = xv[p];
    #pragma unroll
    for (int e = 0; e < 4; ++e)
        *(ulonglong2*)&B1b[bkp * 36 + bf0 + 2 * e] = wv[e];
    __syncthreads();

    float acc1[4][4];
    #pragma unroll
    for (int j = 0; j < 4; ++j)
        #pragma unroll
        for (int e = 0; e < 4; ++e) acc1[j][e] = 0.f;

    // ================= GEMM1: C[64,32] = X[64,512] @ f1slc[512,32] =========
    for (int cb = 0; cb < 8; ++cb) {
        // prefetch chunk cb+1
        if (cb < 7) {
            const int kw = (cb + 1) * 32;
            #pragma unroll
            for (int p = 0; p < 8; ++p)
                xv[p] = __ldg((const ulonglong2*)&g_xsplit[rowb[xr0 + 8 * p] + kw + xw]);
            #pragma unroll
            for (int e = 0; e < 4; ++e)
                wv[e] = __ldg((const ulonglong2*)&f1s[(size_t)(kw + bkp) * 2048 + bf0 + 2 * e]);
        }

        // compute chunk cb
        const ull* Xu  = Xb  + (cb & 1) * 2304;
        const ull* B1u = B1b + (cb & 1) * 1152;
        #pragma unroll
        for (int s = 0; s < 4; ++s) {
            const int kp = s * 8 + c4;
            const ull a0 = Xu[(m0 + gq) * 36 + kp];
            const ull a1 = Xu[(m0 + 8 + gq) * 36 + kp];
            const ull a2 = Xu[(m0 + gq) * 36 + kp + 4];
            const ull a3 = Xu[(m0 + 8 + gq) * 36 + kp + 4];
            #pragma unroll
            for (int j = 0; j < 4; ++j) {
                const ull b0 = B1u[kp * 36 + j * 8 + gq];
                const ull b1 = B1u[(kp + 4) * 36 + j * 8 + gq];
                mma16(acc1[j], ulo(a0), ulo(a1), ulo(a2), ulo(a3), ulo(b0), ulo(b1));
                mma16(acc1[j], ulo(a0), ulo(a1), ulo(a2), ulo(a3), uhi(b0), uhi(b1));
                mma16(acc1[j], uhi(a0), uhi(a1), uhi(a2), uhi(a3), ulo(b0), ulo(b1));
            }
        }

        // stage chunk cb+1
        if (cb < 7) {
            ull* Xu2  = Xb  + ((cb + 1) & 1) * 2304;
            ull* B1u2 = B1b + ((cb + 1) & 1) * 1152;
            #pragma unroll
            for (int p = 0; p < 8; ++p)
                *(ulonglong2*)&Xu2[(xr0 + 8 * p) * 36 + xw] = xv[p];
            #pragma unroll
            for (int e = 0; e < 4; ++e)
                *(ulonglong2*)&B1u2[bkp * 36 + bf0 + 2 * e] = wv[e];
        }
        __syncthreads();
    }

    // ---- relu + split IN REGISTERS -> GEMM2 A-fragments -------------------
    uint32_t yh[2][4], yl[2][4];
    #pragma unroll
    for (int s = 0; s < 2; ++s) {
        const int j0 = 2 * s, j1 = 2 * s + 1;
        ull p;
        p = splitpack(fmaxf(acc1[j0][0], 0.f), fmaxf(acc1[j0][1], 0.f));
        yh[s][0] = ulo(p); yl[s][0] = uhi(p);
        p = splitpack(fmaxf(acc1[j0][2], 0.f), fmaxf(acc1[j0][3], 0.f));
        yh[s][1] = ulo(p); yl[s][1] = uhi(p);
        p = splitpack(fmaxf(acc1[j1][0], 0.f), fmaxf(acc1[j1][1], 0.f));
        yh[s][2] = ulo(p); yl[s][2] = uhi(p);
        p = splitpack(fmaxf(acc1[j1][2], 0.f), fmaxf(acc1[j1][3], 0.f));
        yh[s][3] = ulo(p); yl[s][3] = uhi(p);
    }

    // per-thread output row offsets (float units)
    const int ro0 = rowb[m0 + gq] * 2;
    const int ro1 = rowb[m0 + 8 + gq] * 2;

    // ---- prefetch B2 chunk nc=0
    ulonglong2 pv[8];
    #pragma unroll
    for (int q = 0; q < 8; ++q)
        pv[q] = __ldg((const ulonglong2*)&f2s[2 * q]);
    __syncthreads();   // X reads (chunk 7) done before alias overwrite

    #pragma unroll
    for (int q = 0; q < 8; ++q)
        *(ulonglong2*)&B2b[b2kp * 132 + b2n + 2 * q] = pv[q];
    __syncthreads();

    // ================= GEMM2: Out[64,512] = Y[64,32] @ f2slc[32,512] =======
    for (int nc = 0; nc < 4; ++nc) {
        if (nc < 3) {
            #pragma unroll
            for (int q = 0; q < 8; ++q)
                pv[q] = __ldg((const ulonglong2*)&f2s[(nc + 1) * 128 + 2 * q]);
        }

        const ull* B2u = B2b + (nc & 1) * 2112;
        #pragma unroll 2
        for (int nt = 0; nt < 16; ++nt) {
            const int n0 = nt * 8;
            float acc[4] = {0.f, 0.f, 0.f, 0.f};
            #pragma unroll
            for (int s = 0; s < 2; ++s) {
                const int kp = s * 8 + c4;
                const ull b0 = B2u[kp * 132 + n0 + gq];
                const ull b1 = B2u[(kp + 4) * 132 + n0 + gq];
                mma16(acc, yh[s][0], yh[s][1], yh[s][2], yh[s][3], ulo(b0), ulo(b1));
                mma16(acc, yh[s][0], yh[s][1], yh[s][2], yh[s][3], uhi(b0), uhi(b1));
                mma16(acc, yl[s][0], yl[s][1], yl[s][2], yl[s][3], ulo(b0), ulo(b1));
            }
            const int d = nc * 128 + n0 + 2 * c4;
            atomicAdd((float2*)(out + ro0 + d), make_float2(acc[0], acc[1]));
            atomicAdd((float2*)(out + ro1 + d), make_float2(acc[2], acc[3]));
        }

        if (nc < 3) {
            ull* B2u2 = B2b + ((nc + 1) & 1) * 2112;
            #pragma unroll
            for (int q = 0; q < 8; ++q)
                *(ulonglong2*)&B2u2[b2kp * 132 + b2n + 2 * q] = pv[q];
        }
        __syncthreads();
    }
}

// ---------------------------------------------------------------------------
extern "C" void kernel_launch(void* const* d_in, const int* in_sizes, int n_in,
                              void* d_out, int out_size)
{
    (void)in_sizes; (void)n_in; (void)out_size;
    const float* x    = (const float*)d_in[0];
    const float* ctrl = (const float*)d_in[1];
    const float* f1   = (const float*)d_in[2];
    const float* f2   = (const float*)d_in[3];
    float* out = (float*)d_out;

    const int smem1 = 13312 * 4 + 2048;   // 55296
    cudaFuncSetAttribute(k_route,  cudaFuncAttributeMaxDynamicSharedMemorySize, smem1);
    cudaFuncSetAttribute(k_expert, cudaFuncAttributeMaxDynamicSharedMemorySize, SMEM2);

    k_prep<<<4096, 256>>>(f1, f2);
    k_route<<<NGROUPS, 256, smem1>>>(x, ctrl, out);
    k_expert<<<dim3(8, 64), 128, SMEM2>>>(out);
}

// round 14
// speedup vs baseline: 1.3095x; 1.3095x over previous
#include <cuda_runtime.h>
#include <cuda_fp16.h>
#include <cstdint>

#define NGROUPS 512   // B*S/16
#define NSLOTS  64    // E*Sets
#define DDIM    512
#define TTOK    16
#define FDIM    32

typedef unsigned long long ull;
union U2 { ull u; float2 f; };

// packed fp32x2 FMA (route kernel)
__device__ __forceinline__ void ffma2(ull& d, ull a, ull b) {
    asm("fma.rn.f32x2 %0, %1, %2, %0;" : "+l"(d) : "l"(a), "l"(b));
}
__device__ __forceinline__ ull bcast2(float x) {
    ull r; asm("mov.b64 %0, {%1, %1};" : "=l"(r) : "f"(x)); return r;
}

__device__ int g_winners[NGROUPS * NSLOTS];

// ---------------------------------------------------------------------------
// fp16 helpers
// ---------------------------------------------------------------------------
// pack (v0 -> low half, v1 -> high half)
__device__ __forceinline__ uint32_t f16pair(float v0, float v1) {
    uint32_t r;
    asm("cvt.rn.f16x2.f32 %0, %1, %2;" : "=r"(r) : "f"(v1), "f"(v0));
    return r;
}
// split (v0,v1): low32 = fp16 hi-pair, high32 = fp16 residual-pair
__device__ __forceinline__ ull splitpack16(float v0, float v1) {
    const uint32_t h = f16pair(v0, v1);
    __half2 hh = *(const __half2*)&h;
    const float2 back = __half22float2(hh);
    const uint32_t l = f16pair(v0 - back.x, v1 - back.y);
    return (ull)h | ((ull)l << 32);
}
__device__ __forceinline__ void mma16(float* c, uint32_t a0, uint32_t a1,
                                      uint32_t a2, uint32_t a3,
                                      uint32_t b0, uint32_t b1) {
    asm volatile("mma.sync.aligned.m16n8k16.row.col.f32.f16.f16.f32 "
                 "{%0,%1,%2,%3}, {%4,%5,%6,%7}, {%8,%9}, {%0,%1,%2,%3};"
                 : "+f"(c[0]), "+f"(c[1]), "+f"(c[2]), "+f"(c[3])
                 : "r"(a0), "r"(a1), "r"(a2), "r"(a3), "r"(b0), "r"(b1));
}
__device__ __forceinline__ uint32_t ulo(ull v) { return (uint32_t)v; }
__device__ __forceinline__ uint32_t uhi(ull v) { return (uint32_t)(v >> 32); }

// ---------------------------------------------------------------------------
// Kernel 1: routing (unchanged — proven exact). Zero-inits out.
// ---------------------------------------------------------------------------
__global__ __launch_bounds__(256) void k_route(const float* __restrict__ x,
                                               const float* __restrict__ ctrl,
                                               float* __restrict__ out)
{
    extern __shared__ float sm[];
    float* xs   = sm;
    float* part = sm + 8192;
    float* ls   = sm + 12288;
    double* dred = (double*)(sm + 13312);
    __shared__ int sflags[64];
    __shared__ int swin[64];
    __shared__ int snf;
    __shared__ double dlog[16];

    const int G   = blockIdx.x;
    const int tid = threadIdx.x;
    if (tid == 0) snf = 0;

    const float4* src = (const float4*)(x + (size_t)G * 8192);
    float4* dst = (float4*)(out + (size_t)G * 8192);
    float4* xs4 = (float4*)xs;
    const float4 z4 = make_float4(0.f, 0.f, 0.f, 0.f);
    for (int i = tid; i < 2048; i += 256) { xs4[i] = src[i]; dst[i] = z4; }
    __syncthreads();

    {
        const int sq = tid & 15;
        const int tq = (tid >> 4) & 3;
        const int ks = tid >> 6;
        const int kbase = ks * 128;
        U2 acc[4][2];
        #pragma unroll
        for (int t = 0; t < 4; ++t) { acc[t][0].u = 0ull; acc[t][1].u = 0ull; }
        const float* cbase = ctrl + sq * 4;
        const float* x0 = xs + tq * 4 * DDIM;
        for (int kk = 0; kk < 128; kk += 4) {
            const int k = kbase + kk;
            ulonglong2 w[4];
            #pragma unroll
            for (int j = 0; j < 4; ++j)
                w[j] = __ldg((const ulonglong2*)(cbase + (size_t)(k + j) * 64));
            float xv[4][4];
            #pragma unroll
            for (int t = 0; t < 4; ++t)
                *(float4*)&xv[t][0] = *(const float4*)(x0 + t * DDIM + k);
            #pragma unroll
            for (int j = 0; j < 4; ++j) {
                #pragma unroll
                for (int t = 0; t < 4; ++t) {
                    ull xb = bcast2(xv[t][j]);
                    ffma2(acc[t][0].u, xb, w[j].x);
                    ffma2(acc[t][1].u, xb, w[j].y);
                }
            }
        }
        #pragma unroll
        for (int t = 0; t < 4; ++t) {
            part[tid * 16 + t * 4 + 0] = acc[t][0].f.x;
            part[tid * 16 + t * 4 + 1] = acc[t][0].f.y;
            part[tid * 16 + t * 4 + 2] = acc[t][1].f.x;
            part[tid * 16 + t * 4 + 3] = acc[t][1].f.y;
        }
    }
    __syncthreads();

    {
        const int s   = tid & 63;
        const int tq2 = tid >> 6;
        const int sq2 = s >> 2, sl = s & 3;
        const float step = 1e-6f / 15.f;
        #pragma unroll
        for (int tl = 0; tl < 4; ++tl) {
            float v = 0.f;
            #pragma unroll
            for (int c = 0; c < 4; ++c)
                v += part[(c * 64 + tq2 * 16 + sq2) * 16 + tl * 4 + sl];
            const int t = tq2 * 4 + tl;
            ls[s * 16 + t] = v + step * (float)t;
        }
    }
    __syncthreads();

    if (tid < 64) {
        const int s = tid;
        float best = -3.4e38f, second = -3.4e38f;
        int bi = 0;
        #pragma unroll
        for (int t = 0; t < TTOK; ++t) {
            float v = ls[s * 16 + t];
            if (v >= best) { second = best; best = v; bi = t; }
            else if (v > second) { second = v; }
        }
        swin[s] = bi;
        if (best - second < 2e-5f) { int p = atomicAdd(&snf, 1); sflags[p] = s; }
    }
    __syncthreads();

    const int nf = snf;
    for (int i = 0; i < nf; ++i) {
        const int s = sflags[i];
        const int t = tid >> 4, j = tid & 15;
        double a = 0.0;
        const float* xr = xs + t * DDIM + j * 32;
        const float* cp = ctrl + (size_t)(j * 32) * 64 + s;
        #pragma unroll 8
        for (int k = 0; k < 32; ++k)
            a += (double)xr[k] * (double)__ldg(cp + (size_t)k * 64);
        dred[t * 16 + j] = a;
        __syncthreads();
        if (tid < 16) {
            double tot = 0.0;
            #pragma unroll
            for (int j2 = 0; j2 < 16; ++j2) tot += dred[tid * 16 + j2];
            dlog[tid] = tot + (double)tid * (1e-6 / 15.0);
        }
        __syncthreads();
        if (tid == 0) {
            double best = -1e300; int bi = 0;
            #pragma unroll
            for (int t2 = 0; t2 < TTOK; ++t2)
                if (dlog[t2] >= best) { best = dlog[t2]; bi = t2; }
            swin[s] = bi;
        }
        __syncthreads();
    }
    if (tid < 64) g_winners[G * 64 + tid] = swin[tid];
}

// ---------------------------------------------------------------------------
// Kernel 2: split-fp16 mma.sync expert (2-term), 128 thr / 4 warps, 64 rows.
// GEMM1: X hi-only fp16 (A), f1 split hi+lo (B); 2 mma per k16 step.
// GEMM2: Y split in regs (A), f2 hi-only (B); 2 mma per step.
// Smem word layouts (ull):
//   Xu  [64 row][20]: word P = (a0a2) pair: u32@(kp=8(P>>2)+(P&3)), u32@kp+4
//   B1u [32 kp][36]:  word = (hi-pair(k=2kp,2kp+1)@f , lo-pair@f)
//   B2u [8 P][132]:   word = (hi-pair(f=2kl)@n , hi-pair(f=2kl+8)@n)
// All fragment LDS.64 phases conflict-free (strides 20/36/132 == 4 mod 16).
// ---------------------------------------------------------------------------
#define OFF_ROWB 0
#define OFF_B1   256
#define OFF_X    18688
#define SMEM2    39168

__global__ __launch_bounds__(128, 4) void k_expert(const float* __restrict__ x,
                                                   const float* __restrict__ f1,
                                                   const float* __restrict__ f2,
                                                   float* __restrict__ out)
{
    extern __shared__ __align__(16) char smraw[];
    int* rowb = (int*)(smraw + OFF_ROWB);
    ull* B1b  = (ull*)(smraw + OFF_B1);   // [2][32*36]
    ull* Xb   = (ull*)(smraw + OFF_X);    // [2][64*20]
    ull* B2b  = (ull*)(smraw + OFF_X);    // [2][8*132] alias

    const int slot = blockIdx.y;
    const int g0   = blockIdx.x * 64;
    const int tid  = threadIdx.x;
    const int wid  = tid >> 5;
    const int lane = tid & 31;
    const int gq   = lane >> 2;   // fragment row group 0..7
    const int c4   = lane & 3;    // fragment col group 0..3

    if (tid < 64) {
        const int gg = g0 + tid;
        rowb[tid] = (gg * TTOK + g_winners[gg * 64 + slot]) * DDIM;
    }
    __syncthreads();

    const int m0 = wid * 16;

    // ---- staging maps
    const int xr0 = tid >> 4;                       // X base row (rows xr0+8p)
    const int xP  = tid & 15;                       // X word index P
    const int xkl = ((xP >> 2) << 3) | (xP & 3);    // kp_lo for P
    const int bkp = tid >> 2;                       // B1 k-pair 0..31
    const int bf0 = (tid & 3) * 8;                  // B1 f base (8 f)
    const float* f1b = f1 + slot * 32 + bf0;
    const int b2P  = tid >> 4;                      // B2 word P 0..7
    const int b2kl = ((b2P >> 2) << 3) | (b2P & 3); // f-pair lo
    const int b2n  = (tid & 15) * 8;                // B2 n base (8 n)
    const float* f2b = f2 + (size_t)slot * (FDIM * DDIM) + b2n;

    // ---- prefetch chunk 0
    float2 xa[8], xbv[8];
    float4 w0a, w0b, w1a, w1b;
    #pragma unroll
    for (int p = 0; p < 8; ++p) {
        const float* xp = x + rowb[xr0 + 8 * p] + 2 * xkl;
        xa[p]  = __ldg((const float2*)xp);
        xbv[p] = __ldg((const float2*)(xp + 8));
    }
    {
        const float* r0 = f1b + (size_t)(2 * bkp) * 2048;
        const float* r1 = f1b + (size_t)(2 * bkp + 1) * 2048;
        w0a = __ldg((const float4*)r0);
        w0b = __ldg((const float4*)(r0 + 4));
        w1a = __ldg((const float4*)r1);
        w1b = __ldg((const float4*)(r1 + 4));
    }
    // stage chunk 0 into buf 0
    {
        ull* Xu = Xb;
        #pragma unroll
        for (int p = 0; p < 8; ++p)
            Xu[(xr0 + 8 * p) * 20 + xP] =
                (ull)f16pair(xa[p].x, xa[p].y) | ((ull)f16pair(xbv[p].x, xbv[p].y) << 32);
        ull* B1u = B1b;
        const float* ka0 = (const float*)&w0a;
        const float* ka1 = (const float*)&w0b;
        const float* kb0 = (const float*)&w1a;
        const float* kb1 = (const float*)&w1b;
        #pragma unroll
        for (int e = 0; e < 4; e += 2) {
            ulonglong2 wa, wb;
            wa.x = splitpack16(ka0[e],     kb0[e]);
            wa.y = splitpack16(ka0[e + 1], kb0[e + 1]);
            wb.x = splitpack16(ka1[e],     kb1[e]);
            wb.y = splitpack16(ka1[e + 1], kb1[e + 1]);
            *(ulonglong2*)&B1u[bkp * 36 + bf0 + e] = wa;
            *(ulonglong2*)&B1u[bkp * 36 + bf0 + 4 + e] = wb;
        }
    }
    __syncthreads();

    float acc1[4][4];
    #pragma unroll
    for (int j = 0; j < 4; ++j)
        #pragma unroll
        for (int e = 0; e < 4; ++e) acc1[j][e] = 0.f;

    // ================= GEMM1: C[64,32] = X[64,512] @ f1slc[512,32] =========
    for (int cb = 0; cb < 8; ++cb) {
        // prefetch chunk cb+1
        if (cb < 7) {
            const int kb = (cb + 1) * 64;
            #pragma unroll
            for (int p = 0; p < 8; ++p) {
                const float* xp = x + rowb[xr0 + 8 * p] + kb + 2 * xkl;
                xa[p]  = __ldg((const float2*)xp);
                xbv[p] = __ldg((const float2*)(xp + 8));
            }
            const float* r0 = f1b + (size_t)(kb + 2 * bkp) * 2048;
            const float* r1 = f1b + (size_t)(kb + 2 * bkp + 1) * 2048;
            w0a = __ldg((const float4*)r0);
            w0b = __ldg((const float4*)(r0 + 4));
            w1a = __ldg((const float4*)r1);
            w1b = __ldg((const float4*)(r1 + 4));
        }

        // compute chunk cb
        const ull* Xu  = Xb  + (cb & 1) * 1280;
        const ull* B1u = B1b + (cb & 1) * 1152;
        #pragma unroll
        for (int s = 0; s < 4; ++s) {
            const ull a02 = Xu[(m0 + gq) * 20 + 4 * s + c4];       // (a0,a2)
            const ull a13 = Xu[(m0 + 8 + gq) * 20 + 4 * s + c4];   // (a1,a3)
            const int kp = 8 * s + c4;
            #pragma unroll
            for (int j = 0; j < 4; ++j) {
                const ull W1 = B1u[kp * 36 + j * 8 + gq];          // (b0h,b0l)
                const ull W2 = B1u[(kp + 4) * 36 + j * 8 + gq];    // (b1h,b1l)
                mma16(acc1[j], ulo(a02), ulo(a13), uhi(a02), uhi(a13), ulo(W1), ulo(W2));
                mma16(acc1[j], ulo(a02), ulo(a13), uhi(a02), uhi(a13), uhi(W1), uhi(W2));
            }
        }

        // stage chunk cb+1
        if (cb < 7) {
            ull* Xu2  = Xb  + ((cb + 1) & 1) * 1280;
            ull* B1u2 = B1b + ((cb + 1) & 1) * 1152;
            #pragma unroll
            for (int p = 0; p < 8; ++p)
                Xu2[(xr0 + 8 * p) * 20 + xP] =
                    (ull)f16pair(xa[p].x, xa[p].y) | ((ull)f16pair(xbv[p].x, xbv[p].y) << 32);
            const float* ka0 = (const float*)&w0a;
            const float* ka1 = (const float*)&w0b;
            const float* kb0 = (const float*)&w1a;
            const float* kb1 = (const float*)&w1b;
            #pragma unroll
            for (int e = 0; e < 4; e += 2) {
                ulonglong2 wa, wb;
                wa.x = splitpack16(ka0[e],     kb0[e]);
                wa.y = splitpack16(ka0[e + 1], kb0[e + 1]);
                wb.x = splitpack16(ka1[e],     kb1[e]);
                wb.y = splitpack16(ka1[e + 1], kb1[e + 1]);
                *(ulonglong2*)&B1u2[bkp * 36 + bf0 + e] = wa;
                *(ulonglong2*)&B1u2[bkp * 36 + bf0 + 4 + e] = wb;
            }
        }
        __syncthreads();
    }

    // ---- relu + split-fp16 IN REGISTERS -> GEMM2 A-fragments --------------
    uint32_t yh[2][4], yl[2][4];
    #pragma unroll
    for (int s = 0; s < 2; ++s) {
        const int j0 = 2 * s, j1 = 2 * s + 1;
        ull p;
        p = splitpack16(fmaxf(acc1[j0][0], 0.f), fmaxf(acc1[j0][1], 0.f));
        yh[s][0] = ulo(p); yl[s][0] = uhi(p);
        p = splitpack16(fmaxf(acc1[j0][2], 0.f), fmaxf(acc1[j0][3], 0.f));
        yh[s][1] = ulo(p); yl[s][1] = uhi(p);
        p = splitpack16(fmaxf(acc1[j1][0], 0.f), fmaxf(acc1[j1][1], 0.f));
        yh[s][2] = ulo(p); yl[s][2] = uhi(p);
        p = splitpack16(fmaxf(acc1[j1][2], 0.f), fmaxf(acc1[j1][3], 0.f));
        yh[s][3] = ulo(p); yl[s][3] = uhi(p);
    }

    const int ro0 = rowb[m0 + gq];
    const int ro1 = rowb[m0 + 8 + gq];

    // ---- prefetch B2 chunk nc=0 (hi-only): rows f = 2kl,2kl+1,2kl+8,2kl+9
    float4 v0a, v0b, v1a, v1b, v2a, v2b, v3a, v3b;
    {
        const float* b = f2b;
        v0a = __ldg((const float4*)(b + (size_t)(2 * b2kl)     * DDIM));
        v0b = __ldg((const float4*)(b + (size_t)(2 * b2kl)     * DDIM + 4));
        v1a = __ldg((const float4*)(b + (size_t)(2 * b2kl + 1) * DDIM));
        v1b = __ldg((const float4*)(b + (size_t)(2 * b2kl + 1) * DDIM + 4));
        v2a = __ldg((const float4*)(b + (size_t)(2 * b2kl + 8) * DDIM));
        v2b = __ldg((const float4*)(b + (size_t)(2 * b2kl + 8) * DDIM + 4));
        v3a = __ldg((const float4*)(b + (size_t)(2 * b2kl + 9) * DDIM));
        v3b = __ldg((const float4*)(b + (size_t)(2 * b2kl + 9) * DDIM + 4));
    }

    // stage B2 nc=0 into buf 0 (X reads done at last loop sync)
    {
        ull* B2u = B2b;
        const float* r0 = (const float*)&v0a;
        const float* r0b = (const float*)&v0b;
        const float* r1 = (const float*)&v1a;
        const float* r1b = (const float*)&v1b;
        const float* r2 = (const float*)&v2a;
        const float* r2b = (const float*)&v2b;
        const float* r3 = (const float*)&v3a;
        const float* r3b = (const float*)&v3b;
        #pragma unroll
        for (int e = 0; e < 4; e += 2) {
            ulonglong2 w;
            w.x = (ull)f16pair(r0[e],   r1[e])   | ((ull)f16pair(r2[e],   r3[e])   << 32);
            w.y = (ull)f16pair(r0[e+1], r1[e+1]) | ((ull)f16pair(r2[e+1], r3[e+1]) << 32);
            *(ulonglong2*)&B2u[b2P * 132 + b2n + e] = w;
            ulonglong2 w2;
            w2.x = (ull)f16pair(r0b[e],   r1b[e])   | ((ull)f16pair(r2b[e],   r3b[e])   << 32);
            w2.y = (ull)f16pair(r0b[e+1], r1b[e+1]) | ((ull)f16pair(r2b[e+1], r3b[e+1]) << 32);
            *(ulonglong2*)&B2u[b2P * 132 + b2n + 4 + e] = w2;
        }
    }
    __syncthreads();

    // ================= GEMM2: Out[64,512] = Y[64,32] @ f2slc[32,512] =======
    for (int nc = 0; nc < 4; ++nc) {
        // prefetch next nc
        if (nc < 3) {
            const float* b = f2b + (nc + 1) * 128;
            v0a = __ldg((const float4*)(b + (size_t)(2 * b2kl)     * DDIM));
            v0b = __ldg((const float4*)(b + (size_t)(2 * b2kl)     * DDIM + 4));
            v1a = __ldg((const float4*)(b + (size_t)(2 * b2kl + 1) * DDIM));
            v1b = __ldg((const float4*)(b + (size_t)(2 * b2kl + 1) * DDIM + 4));
            v2a = __ldg((const float4*)(b + (size_t)(2 * b2kl + 8) * DDIM));
            v2b = __ldg((const float4*)(b + (size_t)(2 * b2kl + 8) * DDIM + 4));
            v3a = __ldg((const float4*)(b + (size_t)(2 * b2kl + 9) * DDIM));
            v3b = __ldg((const float4*)(b + (size_t)(2 * b2kl + 9) * DDIM + 4));
        }

        const ull* B2u = B2b + (nc & 1) * 1056;
        #pragma unroll 2
        for (int nt = 0; nt < 16; ++nt) {
            const int n0 = nt * 8;
            float acc[4] = {0.f, 0.f, 0.f, 0.f};
            #pragma unroll
            for (int s = 0; s < 2; ++s) {
                const ull W = B2u[(4 * s + c4) * 132 + n0 + gq];   // (b0,b1)
                mma16(acc, yh[s][0], yh[s][1], yh[s][2], yh[s][3], ulo(W), uhi(W));
                mma16(acc, yl[s][0], yl[s][1], yl[s][2], yl[s][3], ulo(W), uhi(W));
            }
            const int d = nc * 128 + n0 + 2 * c4;
            atomicAdd((float2*)(out + ro0 + d), make_float2(acc[0], acc[1]));
            atomicAdd((float2*)(out + ro1 + d), make_float2(acc[2], acc[3]));
        }
        __syncthreads();   // compute done before restage

        if (nc < 3) {
            ull* B2u2 = B2b + ((nc + 1) & 1) * 1056;
            const float* r0 = (const float*)&v0a;
            const float* r0b = (const float*)&v0b;
            const float* r1 = (const float*)&v1a;
            const float* r1b = (const float*)&v1b;
            const float* r2 = (const float*)&v2a;
            const float* r2b = (const float*)&v2b;
            const float* r3 = (const float*)&v3a;
            const float* r3b = (const float*)&v3b;
            #pragma unroll
            for (int e = 0; e < 4; e += 2) {
                ulonglong2 w;
                w.x = (ull)f16pair(r0[e],   r1[e])   | ((ull)f16pair(r2[e],   r3[e])   << 32);
                w.y = (ull)f16pair(r0[e+1], r1[e+1]) | ((ull)f16pair(r2[e+1], r3[e+1]) << 32);
                *(ulonglong2*)&B2u2[b2P * 132 + b2n + e] = w;
                ulonglong2 w2;
                w2.x = (ull)f16pair(r0b[e],   r1b[e])   | ((ull)f16pair(r2b[e],   r3b[e])   << 32);
                w2.y = (ull)f16pair(r0b[e+1], r1b[e+1]) | ((ull)f16pair(r2b[e+1], r3b[e+1]) << 32);
                *(ulonglong2*)&B2u2[b2P * 132 + b2n + 4 + e] = w2;
            }
            __syncthreads();
        }
    }
}

// ---------------------------------------------------------------------------
extern "C" void kernel_launch(void* const* d_in, const int* in_sizes, int n_in,
                              void* d_out, int out_size)
{
    (void)in_sizes; (void)n_in; (void)out_size;
    const float* x    = (const float*)d_in[0];
    const float* ctrl = (const float*)d_in[1];
    const float* f1   = (const float*)d_in[2];
    const float* f2   = (const float*)d_in[3];
    float* out = (float*)d_out;

    const int smem1 = 13312 * 4 + 2048;   // 55296
    cudaFuncSetAttribute(k_route,  cudaFuncAttributeMaxDynamicSharedMemorySize, smem1);
    cudaFuncSetAttribute(k_expert, cudaFuncAttributeMaxDynamicSharedMemorySize, SMEM2);

    k_route<<<NGROUPS, 256, smem1>>>(x, ctrl, out);
    k_expert<<<dim3(8, 64), 128, SMEM2>>>(x, f1, f2, out);
}

// round 15
// speedup vs baseline: 1.4238x; 1.0872x over previous
#include <cuda_runtime.h>
#include <cuda_fp16.h>
#include <cstdint>

#define NGROUPS 512   // B*S/16
#define NSLOTS  64    // E*Sets
#define DDIM    512
#define TTOK    16
#define FDIM    32

typedef unsigned long long ull;
union U2 { ull u; float2 f; };

// packed fp32x2 FMA (route kernel)
__device__ __forceinline__ void ffma2(ull& d, ull a, ull b) {
    asm("fma.rn.f32x2 %0, %1, %2, %0;" : "+l"(d) : "l"(a), "l"(b));
}
__device__ __forceinline__ ull bcast2(float x) {
    ull r; asm("mov.b64 %0, {%1, %1};" : "=l"(r) : "f"(x)); return r;
}

__device__ int g_winners[NGROUPS * NSLOTS];

// ---------------------------------------------------------------------------
// fp16 helpers
// ---------------------------------------------------------------------------
// pack (v0 -> low half, v1 -> high half)
__device__ __forceinline__ uint32_t f16pair(float v0, float v1) {
    uint32_t r;
    asm("cvt.rn.f16x2.f32 %0, %1, %2;" : "=r"(r) : "f"(v1), "f"(v0));
    return r;
}
// split (v0,v1): low32 = fp16 hi-pair, high32 = fp16 residual-pair
__device__ __forceinline__ ull splitpack16(float v0, float v1) {
    const uint32_t h = f16pair(v0, v1);
    __half2 hh = *(const __half2*)&h;
    const float2 back = __half22float2(hh);
    const uint32_t l = f16pair(v0 - back.x, v1 - back.y);
    return (ull)h | ((ull)l << 32);
}
__device__ __forceinline__ void mma16(float* c, uint32_t a0, uint32_t a1,
                                      uint32_t a2, uint32_t a3,
                                      uint32_t b0, uint32_t b1) {
    asm volatile("mma.sync.aligned.m16n8k16.row.col.f32.f16.f16.f32 "
                 "{%0,%1,%2,%3}, {%4,%5,%6,%7}, {%8,%9}, {%0,%1,%2,%3};"
                 : "+f"(c[0]), "+f"(c[1]), "+f"(c[2]), "+f"(c[3])
                 : "r"(a0), "r"(a1), "r"(a2), "r"(a3), "r"(b0), "r"(b1));
}
__device__ __forceinline__ uint32_t ulo(ull v) { return (uint32_t)v; }
__device__ __forceinline__ uint32_t uhi(ull v) { return (uint32_t)(v >> 32); }

// ---------------------------------------------------------------------------
// Kernel 1: routing (unchanged — proven exact). Zero-inits out.
// ---------------------------------------------------------------------------
__global__ __launch_bounds__(256) void k_route(const float* __restrict__ x,
                                               const float* __restrict__ ctrl,
                                               float* __restrict__ out)
{
    extern __shared__ float sm[];
    float* xs   = sm;
    float* part = sm + 8192;
    float* ls   = sm + 12288;
    double* dred = (double*)(sm + 13312);
    __shared__ int sflags[64];
    __shared__ int swin[64];
    __shared__ int snf;
    __shared__ double dlog[16];

    const int G   = blockIdx.x;
    const int tid = threadIdx.x;
    if (tid == 0) snf = 0;

    const float4* src = (const float4*)(x + (size_t)G * 8192);
    float4* dst = (float4*)(out + (size_t)G * 8192);
    float4* xs4 = (float4*)xs;
    const float4 z4 = make_float4(0.f, 0.f, 0.f, 0.f);
    for (int i = tid; i < 2048; i += 256) { xs4[i] = src[i]; dst[i] = z4; }
    __syncthreads();

    {
        const int sq = tid & 15;
        const int tq = (tid >> 4) & 3;
        const int ks = tid >> 6;
        const int kbase = ks * 128;
        U2 acc[4][2];
        #pragma unroll
        for (int t = 0; t < 4; ++t) { acc[t][0].u = 0ull; acc[t][1].u = 0ull; }
        const float* cbase = ctrl + sq * 4;
        const float* x0 = xs + tq * 4 * DDIM;
        for (int kk = 0; kk < 128; kk += 4) {
            const int k = kbase + kk;
            ulonglong2 w[4];
            #pragma unroll
            for (int j = 0; j < 4; ++j)
                w[j] = __ldg((const ulonglong2*)(cbase + (size_t)(k + j) * 64));
            float xv[4][4];
            #pragma unroll
            for (int t = 0; t < 4; ++t)
                *(float4*)&xv[t][0] = *(const float4*)(x0 + t * DDIM + k);
            #pragma unroll
            for (int j = 0; j < 4; ++j) {
                #pragma unroll
                for (int t = 0; t < 4; ++t) {
                    ull xb = bcast2(xv[t][j]);
                    ffma2(acc[t][0].u, xb, w[j].x);
                    ffma2(acc[t][1].u, xb, w[j].y);
                }
            }
        }
        #pragma unroll
        for (int t = 0; t < 4; ++t) {
            part[tid * 16 + t * 4 + 0] = acc[t][0].f.x;
            part[tid * 16 + t * 4 + 1] = acc[t][0].f.y;
            part[tid * 16 + t * 4 + 2] = acc[t][1].f.x;
            part[tid * 16 + t * 4 + 3] = acc[t][1].f.y;
        }
    }
    __syncthreads();

    {
        const int s   = tid & 63;
        const int tq2 = tid >> 6;
        const int sq2 = s >> 2, sl = s & 3;
        const float step = 1e-6f / 15.f;
        #pragma unroll
        for (int tl = 0; tl < 4; ++tl) {
            float v = 0.f;
            #pragma unroll
            for (int c = 0; c < 4; ++c)
                v += part[(c * 64 + tq2 * 16 + sq2) * 16 + tl * 4 + sl];
            const int t = tq2 * 4 + tl;
            ls[s * 16 + t] = v + step * (float)t;
        }
    }
    __syncthreads();

    if (tid < 64) {
        const int s = tid;
        float best = -3.4e38f, second = -3.4e38f;
        int bi = 0;
        #pragma unroll
        for (int t = 0; t < TTOK; ++t) {
            float v = ls[s * 16 + t];
            if (v >= best) { second = best; best = v; bi = t; }
            else if (v > second) { second = v; }
        }
        swin[s] = bi;
        if (best - second < 2e-5f) { int p = atomicAdd(&snf, 1); sflags[p] = s; }
    }
    __syncthreads();

    const int nf = snf;
    for (int i = 0; i < nf; ++i) {
        const int s = sflags[i];
        const int t = tid >> 4, j = tid & 15;
        double a = 0.0;
        const float* xr = xs + t * DDIM + j * 32;
        const float* cp = ctrl + (size_t)(j * 32) * 64 + s;
        #pragma unroll 8
        for (int k = 0; k < 32; ++k)
            a += (double)xr[k] * (double)__ldg(cp + (size_t)k * 64);
        dred[t * 16 + j] = a;
        __syncthreads();
        if (tid < 16) {
            double tot = 0.0;
            #pragma unroll
            for (int j2 = 0; j2 < 16; ++j2) tot += dred[tid * 16 + j2];
            dlog[tid] = tot + (double)tid * (1e-6 / 15.0);
        }
        __syncthreads();
        if (tid == 0) {
            double best = -1e300; int bi = 0;
            #pragma unroll
            for (int t2 = 0; t2 < TTOK; ++t2)
                if (dlog[t2] >= best) { best = dlog[t2]; bi = t2; }
            swin[s] = bi;
        }
        __syncthreads();
    }
    if (tid < 64) g_winners[G * 64 + tid] = swin[tid];
}

// ---------------------------------------------------------------------------
// Kernel 2: split-fp16 mma.sync expert (2-term), 256 thr / 8 warps, 128 rows.
// Scale-up of the proven R14 structure: warp = one 16-row m-tile x all 32 f;
// f1/f2 staging amortized over 2x rows. Register-Y identity preserved.
// Smem word layouts (ull):
//   Xu  [128 row][20], B1u [32 kp][36], B2u [8 P][132] (alias of X region).
// ---------------------------------------------------------------------------
#define OFF_ROWB 0
#define OFF_B1   512
#define OFF_X    18944
#define SMEM2    59904

__global__ __launch_bounds__(256, 2) void k_expert(const float* __restrict__ x,
                                                   const float* __restrict__ f1,
                                                   const float* __restrict__ f2,
                                                   float* __restrict__ out)
{
    extern __shared__ __align__(16) char smraw[];
    int* rowb = (int*)(smraw + OFF_ROWB);
    ull* B1b  = (ull*)(smraw + OFF_B1);   // [2][32*36]
    ull* Xb   = (ull*)(smraw + OFF_X);    // [2][128*20]
    ull* B2b  = (ull*)(smraw + OFF_X);    // [2][8*132] alias

    const int slot = blockIdx.y;
    const int g0   = blockIdx.x * 128;
    const int tid  = threadIdx.x;
    const int wid  = tid >> 5;
    const int lane = tid & 31;
    const int gq   = lane >> 2;   // fragment row group 0..7
    const int c4   = lane & 3;    // fragment col group 0..3

    if (tid < 128) {
        const int gg = g0 + tid;
        rowb[tid] = (gg * TTOK + g_winners[gg * 64 + slot]) * DDIM;
    }
    __syncthreads();

    const int m0 = wid * 16;      // 8 m-tiles cover 128 rows

    // ---- staging maps (256 threads)
    const int xr0 = tid >> 4;                       // X base row 0..15 (rows xr0+16p, p<8)
    const int xP  = tid & 15;                       // X word index P
    const int xkl = ((xP >> 2) << 3) | (xP & 3);    // kp_lo for P
    const int bkp = tid >> 3;                       // B1 k-pair 0..31
    const int bf0 = (tid & 7) * 4;                  // B1 f base (4 f)
    const float* f1b = f1 + slot * 32 + bf0;
    const int b2P  = tid >> 5;                      // B2 word P 0..7
    const int b2kl = ((b2P >> 2) << 3) | (b2P & 3); // f-pair lo
    const int b2n  = (tid & 31) * 4;                // B2 n base (4 n)
    const float* f2b = f2 + (size_t)slot * (FDIM * DDIM) + b2n;

    // ---- prefetch chunk 0
    float2 xa[8], xbv[8];
    float4 w0a, w1a;
    #pragma unroll
    for (int p = 0; p < 8; ++p) {
        const float* xp = x + rowb[xr0 + 16 * p] + 2 * xkl;
        xa[p]  = __ldg((const float2*)xp);
        xbv[p] = __ldg((const float2*)(xp + 8));
    }
    w0a = __ldg((const float4*)(f1b + (size_t)(2 * bkp) * 2048));
    w1a = __ldg((const float4*)(f1b + (size_t)(2 * bkp + 1) * 2048));

    // stage chunk 0 into buf 0
    {
        ull* Xu = Xb;
        #pragma unroll
        for (int p = 0; p < 8; ++p)
            Xu[(xr0 + 16 * p) * 20 + xP] =
                (ull)f16pair(xa[p].x, xa[p].y) | ((ull)f16pair(xbv[p].x, xbv[p].y) << 32);
        ull* B1u = B1b;
        const float* ka0 = (const float*)&w0a;
        const float* kb0 = (const float*)&w1a;
        #pragma unroll
        for (int e = 0; e < 4; e += 2) {
            ulonglong2 wa;
            wa.x = splitpack16(ka0[e],     kb0[e]);
            wa.y = splitpack16(ka0[e + 1], kb0[e + 1]);
            *(ulonglong2*)&B1u[bkp * 36 + bf0 + e] = wa;
        }
    }
    __syncthreads();

    float acc1[4][4];
    #pragma unroll
    for (int j = 0; j < 4; ++j)
        #pragma unroll
        for (int e = 0; e < 4; ++e) acc1[j][e] = 0.f;

    // ================= GEMM1: C[128,32] = X[128,512] @ f1slc[512,32] =======
    for (int cb = 0; cb < 8; ++cb) {
        // prefetch chunk cb+1
        if (cb < 7) {
            const int kb = (cb + 1) * 64;
            #pragma unroll
            for (int p = 0; p < 8; ++p) {
                const float* xp = x + rowb[xr0 + 16 * p] + kb + 2 * xkl;
                xa[p]  = __ldg((const float2*)xp);
                xbv[p] = __ldg((const float2*)(xp + 8));
            }
            w0a = __ldg((const float4*)(f1b + (size_t)(kb + 2 * bkp) * 2048));
            w1a = __ldg((const float4*)(f1b + (size_t)(kb + 2 * bkp + 1) * 2048));
        }

        // compute chunk cb
        const ull* Xu  = Xb  + (cb & 1) * 2560;
        const ull* B1u = B1b + (cb & 1) * 1152;
        #pragma unroll
        for (int s = 0; s < 4; ++s) {
            const ull a02 = Xu[(m0 + gq) * 20 + 4 * s + c4];       // (a0,a2)
            const ull a13 = Xu[(m0 + 8 + gq) * 20 + 4 * s + c4];   // (a1,a3)
            const int kp = 8 * s + c4;
            #pragma unroll
            for (int j = 0; j < 4; ++j) {
                const ull W1 = B1u[kp * 36 + j * 8 + gq];          // (b0h,b0l)
                const ull W2 = B1u[(kp + 4) * 36 + j * 8 + gq];    // (b1h,b1l)
                mma16(acc1[j], ulo(a02), ulo(a13), uhi(a02), uhi(a13), ulo(W1), ulo(W2));
                mma16(acc1[j], ulo(a02), ulo(a13), uhi(a02), uhi(a13), uhi(W1), uhi(W2));
            }
        }

        // stage chunk cb+1
        if (cb < 7) {
            ull* Xu2  = Xb  + ((cb + 1) & 1) * 2560;
            ull* B1u2 = B1b + ((cb + 1) & 1) * 1152;
            #pragma unroll
            for (int p = 0; p < 8; ++p)
                Xu2[(xr0 + 16 * p) * 20 + xP] =
                    (ull)f16pair(xa[p].x, xa[p].y) | ((ull)f16pair(xbv[p].x, xbv[p].y) << 32);
            const float* ka0 = (const float*)&w0a;
            const float* kb0 = (const float*)&w1a;
            #pragma unroll
            for (int e = 0; e < 4; e += 2) {
                ulonglong2 wa;
                wa.x = splitpack16(ka0[e],     kb0[e]);
                wa.y = splitpack16(ka0[e + 1], kb0[e + 1]);
                *(ulonglong2*)&B1u2[bkp * 36 + bf0 + e] = wa;
            }
        }
        __syncthreads();
    }

    // ---- relu + split-fp16 IN REGISTERS -> GEMM2 A-fragments --------------
    uint32_t yh[2][4], yl[2][4];
    #pragma unroll
    for (int s = 0; s < 2; ++s) {
        const int j0 = 2 * s, j1 = 2 * s + 1;
        ull p;
        p = splitpack16(fmaxf(acc1[j0][0], 0.f), fmaxf(acc1[j0][1], 0.f));
        yh[s][0] = ulo(p); yl[s][0] = uhi(p);
        p = splitpack16(fmaxf(acc1[j0][2], 0.f), fmaxf(acc1[j0][3], 0.f));
        yh[s][1] = ulo(p); yl[s][1] = uhi(p);
        p = splitpack16(fmaxf(acc1[j1][0], 0.f), fmaxf(acc1[j1][1], 0.f));
        yh[s][2] = ulo(p); yl[s][2] = uhi(p);
        p = splitpack16(fmaxf(acc1[j1][2], 0.f), fmaxf(acc1[j1][3], 0.f));
        yh[s][3] = ulo(p); yl[s][3] = uhi(p);
    }

    const int ro0 = rowb[m0 + gq];
    const int ro1 = rowb[m0 + 8 + gq];

    // ---- prefetch B2 chunk nc=0 (hi-only): rows f = 2kl,2kl+1,2kl+8,2kl+9
    float4 v0, v1, v2, v3;
    {
        const float* b = f2b;
        v0 = __ldg((const float4*)(b + (size_t)(2 * b2kl)     * DDIM));
        v1 = __ldg((const float4*)(b + (size_t)(2 * b2kl + 1) * DDIM));
        v2 = __ldg((const float4*)(b + (size_t)(2 * b2kl + 8) * DDIM));
        v3 = __ldg((const float4*)(b + (size_t)(2 * b2kl + 9) * DDIM));
    }

    // stage B2 nc=0 into buf 0 (X reads done at last loop sync)
    {
        ull* B2u = B2b;
        const float* r0 = (const float*)&v0;
        const float* r1 = (const float*)&v1;
        const float* r2 = (const float*)&v2;
        const float* r3 = (const float*)&v3;
        #pragma unroll
        for (int e = 0; e < 4; e += 2) {
            ulonglong2 w;
            w.x = (ull)f16pair(r0[e],   r1[e])   | ((ull)f16pair(r2[e],   r3[e])   << 32);
            w.y = (ull)f16pair(r0[e+1], r1[e+1]) | ((ull)f16pair(r2[e+1], r3[e+1]) << 32);
            *(ulonglong2*)&B2u[b2P * 132 + b2n + e] = w;
        }
    }
    __syncthreads();

    // ================= GEMM2: Out[128,512] = Y[128,32] @ f2slc[32,512] =====
    for (int nc = 0; nc < 4; ++nc) {
        // prefetch next nc
        if (nc < 3) {
            const float* b = f2b + (nc + 1) * 128;
            v0 = __ldg((const float4*)(b + (size_t)(2 * b2kl)     * DDIM));
            v1 = __ldg((const float4*)(b + (size_t)(2 * b2kl + 1) * DDIM));
            v2 = __ldg((const float4*)(b + (size_t)(2 * b2kl + 8) * DDIM));
            v3 = __ldg((const float4*)(b + (size_t)(2 * b2kl + 9) * DDIM));
        }

        const ull* B2u = B2b + (nc & 1) * 1056;
        #pragma unroll 2
        for (int nt = 0; nt < 16; ++nt) {
            const int n0 = nt * 8;
            float acc[4] = {0.f, 0.f, 0.f, 0.f};
            #pragma unroll
            for (int s = 0; s < 2; ++s) {
                const ull W = B2u[(4 * s + c4) * 132 + n0 + gq];   // (b0,b1)
                mma16(acc, yh[s][0], yh[s][1], yh[s][2], yh[s][3], ulo(W), uhi(W));
                mma16(acc, yl[s][0], yl[s][1], yl[s][2], yl[s][3], ulo(W), uhi(W));
            }
            const int d = nc * 128 + n0 + 2 * c4;
            atomicAdd((float2*)(out + ro0 + d), make_float2(acc[0], acc[1]));
            atomicAdd((float2*)(out + ro1 + d), make_float2(acc[2], acc[3]));
        }
        __syncthreads();   // compute done before restage

        if (nc < 3) {
            ull* B2u2 = B2b + ((nc + 1) & 1) * 1056;
            const float* r0 = (const float*)&v0;
            const float* r1 = (const float*)&v1;
            const float* r2 = (const float*)&v2;
            const float* r3 = (const float*)&v3;
            #pragma unroll
            for (int e = 0; e < 4; e += 2) {
                ulonglong2 w;
                w.x = (ull)f16pair(r0[e],   r1[e])   | ((ull)f16pair(r2[e],   r3[e])   << 32);
                w.y = (ull)f16pair(r0[e+1], r1[e+1]) | ((ull)f16pair(r2[e+1], r3[e+1]) << 32);
                *(ulonglong2*)&B2u2[b2P * 132 + b2n + e] = w;
            }
            __syncthreads();
        }
    }
}

// ---------------------------------------------------------------------------
extern "C" void kernel_launch(void* const* d_in, const int* in_sizes, int n_in,
                              void* d_out, int out_size)
{
    (void)in_sizes; (void)n_in; (void)out_size;
    const float* x    = (const float*)d_in[0];
    const float* ctrl = (const float*)d_in[1];
    const float* f1   = (const float*)d_in[2];
    const float* f2   = (const float*)d_in[3];
    float* out = (float*)d_out;

    const int smem1 = 13312 * 4 + 2048;   // 55296
    cudaFuncSetAttribute(k_route,  cudaFuncAttributeMaxDynamicSharedMemorySize, smem1);
    cudaFuncSetAttribute(k_expert, cudaFuncAttributeMaxDynamicSharedMemorySize, SMEM2);

    k_route<<<NGROUPS, 256, smem1>>>(x, ctrl, out);
    k_expert<<<dim3(4, 64), 256, SMEM2>>>(x, f1, f2, out);
}

// round 16
// speedup vs baseline: 1.5134x; 1.0630x over previous
#include <cuda_runtime.h>
#include <cuda_fp16.h>
#include <cstdint>

#define NGROUPS 512   // B*S/16
#define NSLOTS  64    // E*Sets
#define DDIM    512
#define TTOK    16
#define FDIM    32

typedef unsigned long long ull;

__device__ int g_winners[NGROUPS * NSLOTS];

// ---------------------------------------------------------------------------
// fp16 helpers
// ---------------------------------------------------------------------------
__device__ __forceinline__ uint32_t f16pair(float v0, float v1) {
    uint32_t r;
    asm("cvt.rn.f16x2.f32 %0, %1, %2;" : "=r"(r) : "f"(v1), "f"(v0));
    return r;
}
// split (v0,v1): low32 = fp16 hi-pair, high32 = fp16 residual-pair
__device__ __forceinline__ ull splitpack16(float v0, float v1) {
    const uint32_t h = f16pair(v0, v1);
    __half2 hh = *(const __half2*)&h;
    const float2 back = __half22float2(hh);
    const uint32_t l = f16pair(v0 - back.x, v1 - back.y);
    return (ull)h | ((ull)l << 32);
}
__device__ __forceinline__ void mma16(float* c, uint32_t a0, uint32_t a1,
                                      uint32_t a2, uint32_t a3,
                                      uint32_t b0, uint32_t b1) {
    asm volatile("mma.sync.aligned.m16n8k16.row.col.f32.f16.f16.f32 "
                 "{%0,%1,%2,%3}, {%4,%5,%6,%7}, {%8,%9}, {%0,%1,%2,%3};"
                 : "+f"(c[0]), "+f"(c[1]), "+f"(c[2]), "+f"(c[3])
                 : "r"(a0), "r"(a1), "r"(a2), "r"(a3), "r"(b0), "r"(b1));
}
__device__ __forceinline__ uint32_t ulo(ull v) { return (uint32_t)v; }
__device__ __forceinline__ uint32_t uhi(ull v) { return (uint32_t)(v >> 32); }

// ---------------------------------------------------------------------------
// Kernel 1: routing via 3-term split-fp16 mma (error ~2e-7: products of fp16
// splits are exact in fp32 accum; only the 2^-22 ll term is dropped). CTA =
// 4 contiguous groups (M=64 tokens, no gather), N=64 slots, K=512.
// Fp32 logits + tie-breaker -> smem; proven argmax + coop fp64 recheck
// (threshold 2e-5, x re-read from global). Zero-inits the output tile.
// Smem: ls 4*64*17 f32 @0 (17408); Bu [2][32 kp][68] ull @17408 (34816);
//       Xu [2][64 row][36] ull @52224 (36864). Total 89088.
// ---------------------------------------------------------------------------
#define ROFF_LS 0
#define ROFF_B  17408
#define ROFF_X  52224
#define RSMEM   89088

__global__ __launch_bounds__(256) void k_route_mma(const float* __restrict__ x,
                                                   const float* __restrict__ ctrl,
                                                   float* __restrict__ out)
{
    extern __shared__ __align__(16) char smraw[];
    float* ls = (float*)(smraw + ROFF_LS);
    ull*   Bb = (ull*)(smraw + ROFF_B);
    ull*   Xb = (ull*)(smraw + ROFF_X);
    __shared__ int sflags[256];
    __shared__ int swin[256];
    __shared__ int snf;
    __shared__ double dred[256];
    __shared__ double dlog[16];

    const int g0   = blockIdx.x * 4;      // 4 groups per CTA
    const int tid  = threadIdx.x;
    const int wid  = tid >> 5;
    const int lane = tid & 31;
    const int gq   = lane >> 2;
    const int c4   = lane & 3;
    const int mt   = wid & 3;             // m-tile == group index within CTA
    const int nh   = wid >> 2;            // slot half (32)
    const int m0   = mt * 16;

    if (tid == 0) snf = 0;

    // zero-init output tile (4 groups x 16 x 512)
    {
        float4* dst = (float4*)(out + (size_t)g0 * TTOK * DDIM);
        const float4 z4 = make_float4(0.f, 0.f, 0.f, 0.f);
        for (int i = tid; i < 8192; i += 256) dst[i] = z4;
    }

    const float* xbase = x + (size_t)g0 * TTOK * DDIM;   // 64 contiguous rows

    // staging maps
    const int xr = tid >> 2;             // row 0..63
    const int xq = tid & 3;              // k-quarter (16 k)
    const int bkp = tid >> 3;            // ctrl k-pair 0..31
    const int bf0 = (tid & 7) * 8;       // 8 slots

    // ---- prefetch chunk 0
    float4 xv[4];
    float4 c0a, c0b, c1a, c1b;
    #pragma unroll
    for (int q = 0; q < 4; ++q)
        xv[q] = __ldg((const float4*)(xbase + xr * DDIM + xq * 16 + q * 4));
    {
        const float* r0 = ctrl + (size_t)(2 * bkp) * 64 + bf0;
        const float* r1 = ctrl + (size_t)(2 * bkp + 1) * 64 + bf0;
        c0a = __ldg((const float4*)r0); c0b = __ldg((const float4*)(r0 + 4));
        c1a = __ldg((const float4*)r1); c1b = __ldg((const float4*)(r1 + 4));
    }
    // stage chunk 0 into buf 0
    {
        const float* xe = (const float*)xv;
        #pragma unroll
        for (int i = 0; i < 8; ++i)
            Xb[xr * 36 + xq * 8 + i] = splitpack16(xe[2 * i], xe[2 * i + 1]);
        const float* e0 = (const float*)&c0a;   // + c0b behind it (8 floats)
        const float* e1 = (const float*)&c1a;
        #pragma unroll
        for (int e = 0; e < 4; ++e) {
            Bb[bkp * 68 + bf0 + e]     = splitpack16(e0[e], e1[e]);
            Bb[bkp * 68 + bf0 + 4 + e] = splitpack16(((const float*)&c0b)[e],
                                                     ((const float*)&c1b)[e]);
        }
    }
    __syncthreads();

    float acc1[4][4];
    #pragma unroll
    for (int j = 0; j < 4; ++j)
        #pragma unroll
        for (int e = 0; e < 4; ++e) acc1[j][e] = 0.f;

    // ---- main loop: logits[64,64] = X[64,512] @ ctrl[512,64]
    for (int cb = 0; cb < 8; ++cb) {
        if (cb < 7) {
            const int kb = (cb + 1) * 64;
            #pragma unroll
            for (int q = 0; q < 4; ++q)
                xv[q] = __ldg((const float4*)(xbase + xr * DDIM + kb + xq * 16 + q * 4));
            const float* r0 = ctrl + (size_t)(kb + 2 * bkp) * 64 + bf0;
            const float* r1 = ctrl + (size_t)(kb + 2 * bkp + 1) * 64 + bf0;
            c0a = __ldg((const float4*)r0); c0b = __ldg((const float4*)(r0 + 4));
            c1a = __ldg((const float4*)r1); c1b = __ldg((const float4*)(r1 + 4));
        }

        const ull* Xu = Xb + (cb & 1) * 2304;
        const ull* Bu = Bb + (cb & 1) * 2176;
        #pragma unroll
        for (int s = 0; s < 4; ++s) {
            const int kp = s * 8 + c4;
            const ull a0 = Xu[(m0 + gq) * 36 + kp];
            const ull a1 = Xu[(m0 + 8 + gq) * 36 + kp];
            const ull a2 = Xu[(m0 + gq) * 36 + kp + 4];
            const ull a3 = Xu[(m0 + 8 + gq) * 36 + kp + 4];
            #pragma unroll
            for (int j = 0; j < 4; ++j) {
                const int n0 = nh * 32 + j * 8;
                const ull W1 = Bu[kp * 68 + n0 + gq];
                const ull W2 = Bu[(kp + 4) * 68 + n0 + gq];
                mma16(acc1[j], ulo(a0), ulo(a1), ulo(a2), ulo(a3), ulo(W1), ulo(W2));
                mma16(acc1[j], ulo(a0), ulo(a1), ulo(a2), ulo(a3), uhi(W1), uhi(W2));
                mma16(acc1[j], uhi(a0), uhi(a1), uhi(a2), uhi(a3), ulo(W1), ulo(W2));
            }
        }

        if (cb < 7) {
            ull* Xu2 = Xb + ((cb + 1) & 1) * 2304;
            ull* Bu2 = Bb + ((cb + 1) & 1) * 2176;
            const float* xe = (const float*)xv;
            #pragma unroll
            for (int i = 0; i < 8; ++i)
                Xu2[xr * 36 + xq * 8 + i] = splitpack16(xe[2 * i], xe[2 * i + 1]);
            #pragma unroll
            for (int e = 0; e < 4; ++e) {
                Bu2[bkp * 68 + bf0 + e]     = splitpack16(((const float*)&c0a)[e],
                                                          ((const float*)&c1a)[e]);
                Bu2[bkp * 68 + bf0 + 4 + e] = splitpack16(((const float*)&c0b)[e],
                                                          ((const float*)&c1b)[e]);
            }
        }
        __syncthreads();
    }

    // ---- epilogue: logits + tie-breaker into ls[g][slot][token] (pad 17)
    {
        const float step = 1e-6f / 15.f;
        #pragma unroll
        for (int j = 0; j < 4; ++j) {
            #pragma unroll
            for (int e = 0; e < 4; ++e) {
                const int slot  = nh * 32 + j * 8 + 2 * c4 + (e & 1);
                const int token = gq + 8 * (e >> 1);
                ls[(mt * 64 + slot) * 17 + token] = acc1[j][e] + step * (float)token;
            }
        }
    }
    __syncthreads();

    // ---- argmax per (group, slot); flag near-ties
    {
        const int g = tid >> 6, s = tid & 63;
        const float* lp = ls + (g * 64 + s) * 17;
        float best = -3.4e38f, second = -3.4e38f;
        int bi = 0;
        #pragma unroll
        for (int t = 0; t < TTOK; ++t) {
            const float v = lp[t];
            if (v >= best) { second = best; best = v; bi = t; }
            else if (v > second) { second = v; }
        }
        swin[tid] = bi;
        if (best - second < 2e-5f) { int p = atomicAdd(&snf, 1); sflags[p] = tid; }
    }
    __syncthreads();

    // ---- cooperative fp64 recheck of flagged slots (rare)
    const int nf = snf;
    for (int i = 0; i < nf; ++i) {
        const int sfl = sflags[i];
        const int g2 = sfl >> 6, s2 = sfl & 63;
        const int t = tid >> 4, j = tid & 15;
        double a = 0.0;
        const float* xr2 = x + ((size_t)(g0 + g2) * TTOK + t) * DDIM + j * 32;
        const float* cp  = ctrl + (size_t)(j * 32) * 64 + s2;
        #pragma unroll 8
        for (int k = 0; k < 32; ++k)
            a += (double)__ldg(xr2 + k) * (double)__ldg(cp + (size_t)k * 64);
        dred[t * 16 + j] = a;
        __syncthreads();
        if (tid < 16) {
            double tot = 0.0;
            #pragma unroll
            for (int j2 = 0; j2 < 16; ++j2) tot += dred[tid * 16 + j2];
            dlog[tid] = tot + (double)tid * (1e-6 / 15.0);
        }
        __syncthreads();
        if (tid == 0) {
            double best = -1e300; int bi = 0;
            #pragma unroll
            for (int t2 = 0; t2 < TTOK; ++t2)
                if (dlog[t2] >= best) { best = dlog[t2]; bi = t2; }
            swin[sfl] = bi;
        }
        __syncthreads();
    }

    g_winners[(g0 + (tid >> 6)) * 64 + (tid & 63)] = swin[tid];
}

// ---------------------------------------------------------------------------
// Kernel 2: split-fp16 mma.sync expert (2-term), 256 thr / 8 warps, 128 rows.
// (unchanged from R15 — proven: 42.6us, rel_err 2.93e-4)
// ---------------------------------------------------------------------------
#define OFF_ROWB 0
#define OFF_B1   512
#define OFF_X    18944
#define SMEM2    59904

__global__ __launch_bounds__(256, 2) void k_expert(const float* __restrict__ x,
                                                   const float* __restrict__ f1,
                                                   const float* __restrict__ f2,
                                                   float* __restrict__ out)
{
    extern __shared__ __align__(16) char smraw[];
    int* rowb = (int*)(smraw + OFF_ROWB);
    ull* B1b  = (ull*)(smraw + OFF_B1);   // [2][32*36]
    ull* Xb   = (ull*)(smraw + OFF_X);    // [2][128*20]
    ull* B2b  = (ull*)(smraw + OFF_X);    // [2][8*132] alias

    const int slot = blockIdx.y;
    const int g0   = blockIdx.x * 128;
    const int tid  = threadIdx.x;
    const int wid  = tid >> 5;
    const int lane = tid & 31;
    const int gq   = lane >> 2;
    const int c4   = lane & 3;

    if (tid < 128) {
        const int gg = g0 + tid;
        rowb[tid] = (gg * TTOK + g_winners[gg * 64 + slot]) * DDIM;
    }
    __syncthreads();

    const int m0 = wid * 16;

    const int xr0 = tid >> 4;
    const int xP  = tid & 15;
    const int xkl = ((xP >> 2) << 3) | (xP & 3);
    const int bkp = tid >> 3;
    const int bf0 = (tid & 7) * 4;
    const float* f1b = f1 + slot * 32 + bf0;
    const int b2P  = tid >> 5;
    const int b2kl = ((b2P >> 2) << 3) | (b2P & 3);
    const int b2n  = (tid & 31) * 4;
    const float* f2b = f2 + (size_t)slot * (FDIM * DDIM) + b2n;

    float2 xa[8], xbv[8];
    float4 w0a, w1a;
    #pragma unroll
    for (int p = 0; p < 8; ++p) {
        const float* xp = x + rowb[xr0 + 16 * p] + 2 * xkl;
        xa[p]  = __ldg((const float2*)xp);
        xbv[p] = __ldg((const float2*)(xp + 8));
    }
    w0a = __ldg((const float4*)(f1b + (size_t)(2 * bkp) * 2048));
    w1a = __ldg((const float4*)(f1b + (size_t)(2 * bkp + 1) * 2048));

    {
        ull* Xu = Xb;
        #pragma unroll
        for (int p = 0; p < 8; ++p)
            Xu[(xr0 + 16 * p) * 20 + xP] =
                (ull)f16pair(xa[p].x, xa[p].y) | ((ull)f16pair(xbv[p].x, xbv[p].y) << 32);
        ull* B1u = B1b;
        const float* ka0 = (const float*)&w0a;
        const float* kb0 = (const float*)&w1a;
        #pragma unroll
        for (int e = 0; e < 4; e += 2) {
            ulonglong2 wa;
            wa.x = splitpack16(ka0[e],     kb0[e]);
            wa.y = splitpack16(ka0[e + 1], kb0[e + 1]);
            *(ulonglong2*)&B1u[bkp * 36 + bf0 + e] = wa;
        }
    }
    __syncthreads();

    float acc1[4][4];
    #pragma unroll
    for (int j = 0; j < 4; ++j)
        #pragma unroll
        for (int e = 0; e < 4; ++e) acc1[j][e] = 0.f;

    for (int cb = 0; cb < 8; ++cb) {
        if (cb < 7) {
            const int kb = (cb + 1) * 64;
            #pragma unroll
            for (int p = 0; p < 8; ++p) {
                const float* xp = x + rowb[xr0 + 16 * p] + kb + 2 * xkl;
                xa[p]  = __ldg((const float2*)xp);
                xbv[p] = __ldg((const float2*)(xp + 8));
            }
            w0a = __ldg((const float4*)(f1b + (size_t)(kb + 2 * bkp) * 2048));
            w1a = __ldg((const float4*)(f1b + (size_t)(kb + 2 * bkp + 1) * 2048));
        }

        const ull* Xu  = Xb  + (cb & 1) * 2560;
        const ull* B1u = B1b + (cb & 1) * 1152;
        #pragma unroll
        for (int s = 0; s < 4; ++s) {
            const ull a02 = Xu[(m0 + gq) * 20 + 4 * s + c4];
            const ull a13 = Xu[(m0 + 8 + gq) * 20 + 4 * s + c4];
            const int kp = 8 * s + c4;
            #pragma unroll
            for (int j = 0; j < 4; ++j) {
                const ull W1 = B1u[kp * 36 + j * 8 + gq];
                const ull W2 = B1u[(kp + 4) * 36 + j * 8 + gq];
                mma16(acc1[j], ulo(a02), ulo(a13), uhi(a02), uhi(a13), ulo(W1), ulo(W2));
                mma16(acc1[j], ulo(a02), ulo(a13), uhi(a02), uhi(a13), uhi(W1), uhi(W2));
            }
        }

        if (cb < 7) {
            ull* Xu2  = Xb  + ((cb + 1) & 1) * 2560;
            ull* B1u2 = B1b + ((cb + 1) & 1) * 1152;
            #pragma unroll
            for (int p = 0; p < 8; ++p)
                Xu2[(xr0 + 16 * p) * 20 + xP] =
                    (ull)f16pair(xa[p].x, xa[p].y) | ((ull)f16pair(xbv[p].x, xbv[p].y) << 32);
            const float* ka0 = (const float*)&w0a;
            const float* kb0 = (const float*)&w1a;
            #pragma unroll
            for (int e = 0; e < 4; e += 2) {
                ulonglong2 wa;
                wa.x = splitpack16(ka0[e],     kb0[e]);
                wa.y = splitpack16(ka0[e + 1], kb0[e + 1]);
                *(ulonglong2*)&B1u2[bkp * 36 + bf0 + e] = wa;
            }
        }
        __syncthreads();
    }

    uint32_t yh[2][4], yl[2][4];
    #pragma unroll
    for (int s = 0; s < 2; ++s) {
        const int j0 = 2 * s, j1 = 2 * s + 1;
        ull p;
        p = splitpack16(fmaxf(acc1[j0][0], 0.f), fmaxf(acc1[j0][1], 0.f));
        yh[s][0] = ulo(p); yl[s][0] = uhi(p);
        p = splitpack16(fmaxf(acc1[j0][2], 0.f), fmaxf(acc1[j0][3], 0.f));
        yh[s][1] = ulo(p); yl[s][1] = uhi(p);
        p = splitpack16(fmaxf(acc1[j1][0], 0.f), fmaxf(acc1[j1][1], 0.f));
        yh[s][2] = ulo(p); yl[s][2] = uhi(p);
        p = splitpack16(fmaxf(acc1[j1][2], 0.f), fmaxf(acc1[j1][3], 0.f));
        yh[s][3] = ulo(p); yl[s][3] = uhi(p);
    }

    const int ro0 = rowb[m0 + gq];
    const int ro1 = rowb[m0 + 8 + gq];

    float4 v0, v1, v2, v3;
    {
        const float* b = f2b;
        v0 = __ldg((const float4*)(b + (size_t)(2 * b2kl)     * DDIM));
        v1 = __ldg((const float4*)(b + (size_t)(2 * b2kl + 1) * DDIM));
        v2 = __ldg((const float4*)(b + (size_t)(2 * b2kl + 8) * DDIM));
        v3 = __ldg((const float4*)(b + (size_t)(2 * b2kl + 9) * DDIM));
    }

    {
        ull* B2u = B2b;
        const float* r0 = (const float*)&v0;
        const float* r1 = (const float*)&v1;
        const float* r2 = (const float*)&v2;
        const float* r3 = (const float*)&v3;
        #pragma unroll
        for (int e = 0; e < 4; e += 2) {
            ulonglong2 w;
            w.x = (ull)f16pair(r0[e],   r1[e])   | ((ull)f16pair(r2[e],   r3[e])   << 32);
            w.y = (ull)f16pair(r0[e+1], r1[e+1]) | ((ull)f16pair(r2[e+1], r3[e+1]) << 32);
            *(ulonglong2*)&B2u[b2P * 132 + b2n + e] = w;
        }
    }
    __syncthreads();

    for (int nc = 0; nc < 4; ++nc) {
        if (nc < 3) {
            const float* b = f2b + (nc + 1) * 128;
            v0 = __ldg((const float4*)(b + (size_t)(2 * b2kl)     * DDIM));
            v1 = __ldg((const float4*)(b + (size_t)(2 * b2kl + 1) * DDIM));
            v2 = __ldg((const float4*)(b + (size_t)(2 * b2kl + 8) * DDIM));
            v3 = __ldg((const float4*)(b + (size_t)(2 * b2kl + 9) * DDIM));
        }

        const ull* B2u = B2b + (nc & 1) * 1056;
        #pragma unroll 2
        for (int nt = 0; nt < 16; ++nt) {
            const int n0 = nt * 8;
            float acc[4] = {0.f, 0.f, 0.f, 0.f};
            #pragma unroll
            for (int s = 0; s < 2; ++s) {
                const ull W = B2u[(4 * s + c4) * 132 + n0 + gq];
                mma16(acc, yh[s][0], yh[s][1], yh[s][2], yh[s][3], ulo(W), uhi(W));
                mma16(acc, yl[s][0], yl[s][1], yl[s][2], yl[s][3], ulo(W), uhi(W));
            }
            const int d = nc * 128 + n0 + 2 * c4;
            atomicAdd((float2*)(out + ro0 + d), make_float2(acc[0], acc[1]));
            atomicAdd((float2*)(out + ro1 + d), make_float2(acc[2], acc[3]));
        }
        __syncthreads();

        if (nc < 3) {
            ull* B2u2 = B2b + ((nc + 1) & 1) * 1056;
            const float* r0 = (const float*)&v0;
            const float* r1 = (const float*)&v1;
            const float* r2 = (const float*)&v2;
            const float* r3 = (const float*)&v3;
            #pragma unroll
            for (int e = 0; e < 4; e += 2) {
                ulonglong2 w;
                w.x = (ull)f16pair(r0[e],   r1[e])   | ((ull)f16pair(r2[e],   r3[e])   << 32);
                w.y = (ull)f16pair(r0[e+1], r1[e+1]) | ((ull)f16pair(r2[e+1], r3[e+1]) << 32);
                *(ulonglong2*)&B2u2[b2P * 132 + b2n + e] = w;
            }
            __syncthreads();
        }
    }
}

// ---------------------------------------------------------------------------
extern "C" void kernel_launch(void* const* d_in, const int* in_sizes, int n_in,
                              void* d_out, int out_size)
{
    (void)in_sizes; (void)n_in; (void)out_size;
    const float* x    = (const float*)d_in[0];
    const float* ctrl = (const float*)d_in[1];
    const float* f1   = (const float*)d_in[2];
    const float* f2   = (const float*)d_in[3];
    float* out = (float*)d_out;

    cudaFuncSetAttribute(k_route_mma, cudaFuncAttributeMaxDynamicSharedMemorySize, RSMEM);
    cudaFuncSetAttribute(k_expert,    cudaFuncAttributeMaxDynamicSharedMemorySize, SMEM2);

    k_route_mma<<<NGROUPS / 4, 256, RSMEM>>>(x, ctrl, out);
    k_expert<<<dim3(4, 64), 256, SMEM2>>>(x, f1, f2, out);
}